// round 17
// baseline (speedup 1.0000x reference)
#include <cuda_runtime.h>
#include <cstdint>

// Problem constants
#define SQ   2048
#define DK   64
#define NBH  64
#define NB   4
#define TM   16          // query rows per CTA
#define TN   128         // key/value cols per tile
#define NTHREADS 256
#define NTILES (SQ / TN) // 16

// Padded strides (floats) — conflict-free MMA fragment loads
#define SS_STRIDE 2052   // bank = 4*gid + tig (+off) distinct; rows 16B-aligned
#define KT_STRIDE 136    // K tile [64][136]: bank = 8*tig + gid + n0 distinct
#define VT_STRIDE 72     // V tile [128][72]: bank = 8*tig + gid + n0 distinct
#define QT_STRIDE 72

// Round-to-nearest on the 13 mantissa bits the tf32 MMA truncates:
// integer +0x1000 carries correctly through mantissa into exponent.
#define TF32_RN(u) ((u) + 0x1000u)

__device__ unsigned char g_mask[NB * SQ];

// ---------------------------------------------------------------------------
// Mask canonicalization (dtype-agnostic -> uint8 0/1). Proven since R7.
// ---------------------------------------------------------------------------
__global__ void mask_canon_kernel(const unsigned char* __restrict__ mraw)
{
    __shared__ int flagGT1, flagOff;
    const int tid = threadIdx.x;
    if (tid == 0) { flagGT1 = 0; flagOff = 0; }
    __syncthreads();

    int lGT1 = 0, lOff = 0;
    for (int i = tid; i < NB * SQ; i += NTHREADS) {
        unsigned char b = mraw[i];
        if (b > 1)        lGT1 = 1;
        if ((i & 3) && b) lOff = 1;
    }
    if (lGT1) atomicOr(&flagGT1, 1);
    if (lOff) atomicOr(&flagOff, 1);
    __syncthreads();

    if (flagGT1) {
        const float* mf = reinterpret_cast<const float*>(mraw);
        for (int i = tid; i < NB * SQ; i += NTHREADS)
            g_mask[i] = (mf[i] != 0.0f) ? 1 : 0;
    } else if (flagOff) {
        for (int i = tid; i < NB * SQ; i += NTHREADS)
            g_mask[i] = mraw[i] ? 1 : 0;
    } else {
        const int* mi = reinterpret_cast<const int*>(mraw);
        for (int i = tid; i < NB * SQ; i += NTHREADS)
            g_mask[i] = (mi[i] != 0) ? 1 : 0;
    }
}

// Shared memory (~204.8 KB). Double-buffered K/V stages; sV stage 0 is reused
// as the phase-3 partial buffer pbuf[8][16][64] (32 KB).
struct Smem {
    float sS[TM * SS_STRIDE];                 // 131,328 B
    union {
        float sK[2][64 * KT_STRIDE];          // 2 x 34,816 B
        float sV[2][TN * VT_STRIDE];          // 2 x 36,864 B
    };
    float sQ[TM * QT_STRIDE];                 //   4,608 B
    float sInv[TM];
};

__device__ __forceinline__ uint32_t f2tf32_rna(float x) {
    uint32_t r;
    asm("cvt.rna.tf32.f32 %0, %1;" : "=r"(r) : "f"(x));
    return r;
}
__device__ __forceinline__ float rna_f(float x) {
    return __uint_as_float(f2tf32_rna(x));
}

#define CP_ASYNC16(dst_u32, src_ptr) \
    asm volatile("cp.async.cg.shared.global [%0], [%1], 16;\n" \
                 :: "r"(dst_u32), "l"(src_ptr))
#define CP_COMMIT() asm volatile("cp.async.commit_group;\n" ::: "memory")
#define CP_WAIT(N)  asm volatile("cp.async.wait_group %0;\n" :: "n"(N) : "memory")

__device__ __forceinline__ void mma_tf32(float* d,
                                         uint32_t a0, uint32_t a1, uint32_t a2, uint32_t a3,
                                         uint32_t b0, uint32_t b1)
{
    asm volatile(
        "mma.sync.aligned.m16n8k8.row.col.f32.tf32.tf32.f32 "
        "{%0,%1,%2,%3}, {%4,%5,%6,%7}, {%8,%9}, {%0,%1,%2,%3};\n"
        : "+f"(d[0]), "+f"(d[1]), "+f"(d[2]), "+f"(d[3])
        : "r"(a0), "r"(a1), "r"(a2), "r"(a3), "r"(b0), "r"(b1));
}

__global__ __launch_bounds__(NTHREADS, 1)
void sdpa_tc_kernel(const float* __restrict__ q,
                    const float* __restrict__ k,
                    const float* __restrict__ v,
                    float* __restrict__ out_ctx,
                    float* __restrict__ out_attn)
{
    extern __shared__ char smem_raw[];
    Smem& sm = *reinterpret_cast<Smem*>(smem_raw);

    const int bh   = blockIdx.y;
    const int row0 = blockIdx.x * TM;
    const int b    = bh >> 4;
    const int tid  = threadIdx.x;
    const int warp = tid >> 5;
    const int lane = tid & 31;
    const int gid  = lane >> 2;   // 0..7
    const int tig  = lane & 3;    // 0..3

    const float* __restrict__ Q  = q + (size_t)bh * SQ * DK;
    const float* __restrict__ K  = k + (size_t)bh * DK * SQ;   // [d][t]
    const float* __restrict__ V  = v + (size_t)bh * SQ * DK;   // [t][d]
    const unsigned char* __restrict__ Mk = g_mask + (size_t)b * SQ;

    const int i0 = tid;   // cp.async float4 slot base

    // ---------- Load Q tile (16 x 64) into sQ ----------
    {
        int r  = tid & 15;
        int d0 = (tid >> 4) * 4;
        float4 qv = *reinterpret_cast<const float4*>(Q + (size_t)(row0 + r) * DK + d0);
        float* dst = &sm.sQ[r * QT_STRIDE + d0];
        dst[0] = qv.x; dst[1] = qv.y; dst[2] = qv.z; dst[3] = qv.w;
    }
    __syncthreads();

    // ---------- Preload Q as RNA tf32 fragments ----------
    uint32_t aq[8][4];
    #pragma unroll
    for (int kc = 0; kc < 8; ++kc) {
        #pragma unroll
        for (int e = 0; e < 4; ++e) {
            int r = (e & 1) ? gid + 8 : gid;
            int c = kc * 8 + tig + ((e & 2) ? 4 : 0);
            aq[kc][e] = f2tf32_rna(sm.sQ[r * QT_STRIDE + c]);
        }
    }

    // ---------- Phase 1: scores = (Q K) * scale, masked -> sS ----------
    // Double-buffered cp.async fills; RN via +0x1000 on b-fragments.
    {
        const float scale = 0.125f;

        #pragma unroll
        for (int j = 0; j < 8; ++j) {
            int i  = i0 + j * NTHREADS;
            int d  = i >> 5;
            int c4 = (i & 31) << 2;
            uint32_t dst = (uint32_t)__cvta_generic_to_shared(&sm.sK[0][d * KT_STRIDE + c4]);
            CP_ASYNC16(dst, K + (size_t)d * SQ + c4);
        }
        CP_COMMIT();

        #pragma unroll 1
        for (int jt = 0; jt < NTILES; ++jt) {
            const int stage = jt & 1;
            if (jt + 1 < NTILES) {
                const int t1 = (jt + 1) * TN;
                const int nstage = stage ^ 1;
                #pragma unroll
                for (int j = 0; j < 8; ++j) {
                    int i  = i0 + j * NTHREADS;
                    int d  = i >> 5;
                    int c4 = (i & 31) << 2;
                    uint32_t dst = (uint32_t)__cvta_generic_to_shared(
                        &sm.sK[nstage][d * KT_STRIDE + c4]);
                    CP_ASYNC16(dst, K + (size_t)d * SQ + t1 + c4);
                }
                CP_COMMIT();
                CP_WAIT(1);
            } else {
                CP_WAIT(0);
            }
            __syncthreads();

            const float* __restrict__ sK = sm.sK[stage];
            const int t0 = jt * TN;
            const int nbase = warp * 16;
            float acc[2][2][4];
            #pragma unroll
            for (int nb = 0; nb < 2; ++nb)
                #pragma unroll
                for (int p = 0; p < 2; ++p)
                    #pragma unroll
                    for (int e = 0; e < 4; ++e) acc[nb][p][e] = 0.f;

            #pragma unroll
            for (int kc = 0; kc < 8; ++kc) {
                const int par = kc & 1;
                #pragma unroll
                for (int nb = 0; nb < 2; ++nb) {
                    const int n0 = nbase + nb * 8;
                    uint32_t b0 = TF32_RN(__float_as_uint(sK[(kc * 8 + tig    ) * KT_STRIDE + n0 + gid]));
                    uint32_t b1 = TF32_RN(__float_as_uint(sK[(kc * 8 + tig + 4) * KT_STRIDE + n0 + gid]));
                    mma_tf32(acc[nb][par], aq[kc][0], aq[kc][1], aq[kc][2], aq[kc][3], b0, b1);
                }
            }

            #pragma unroll
            for (int nb = 0; nb < 2; ++nb) {
                const int n0 = nbase + nb * 8;
                float c0 = acc[nb][0][0] + acc[nb][1][0];
                float c1 = acc[nb][0][1] + acc[nb][1][1];
                float c2 = acc[nb][0][2] + acc[nb][1][2];
                float c3 = acc[nb][0][3] + acc[nb][1][3];
                const int tc0 = t0 + n0 + 2 * tig;
                unsigned char m0 = Mk[tc0], m1 = Mk[tc0 + 1];
                float2 s0, s1;
                s0.x = m0 ? -1e9f : c0 * scale;
                s0.y = m1 ? -1e9f : c1 * scale;
                s1.x = m0 ? -1e9f : c2 * scale;
                s1.y = m1 ? -1e9f : c3 * scale;
                *reinterpret_cast<float2*>(&sm.sS[ gid      * SS_STRIDE + tc0]) = s0;
                *reinterpret_cast<float2*>(&sm.sS[(gid + 8) * SS_STRIDE + tc0]) = s1;
            }
            __syncthreads();
        }
    }

    // ---------- Phase 2: softmax; p = RNA(exp(s - m)) in place ----------
    // RNA keeps phase-3 a-fragments exact on the tf32 grid.
    {
        #pragma unroll
        for (int rr = 0; rr < 2; ++rr) {
            int r = warp * 2 + rr;
            float* row = &sm.sS[r * SS_STRIDE];
            float m = -3.4e38f;
            for (int i = lane * 4; i < SQ; i += 128) {
                float4 sv = *reinterpret_cast<const float4*>(&row[i]);
                m = fmaxf(m, fmaxf(fmaxf(sv.x, sv.y), fmaxf(sv.z, sv.w)));
            }
            #pragma unroll
            for (int o = 16; o > 0; o >>= 1) m = fmaxf(m, __shfl_xor_sync(0xffffffffu, m, o));

            float l = 0.f;
            for (int i = lane * 4; i < SQ; i += 128) {
                float4 sv = *reinterpret_cast<float4*>(&row[i]);
                sv.x = rna_f(__expf(sv.x - m));
                sv.y = rna_f(__expf(sv.y - m));
                sv.z = rna_f(__expf(sv.z - m));
                sv.w = rna_f(__expf(sv.w - m));
                l += (sv.x + sv.y) + (sv.z + sv.w);
                *reinterpret_cast<float4*>(&row[i]) = sv;
            }
            #pragma unroll
            for (int o = 16; o > 0; o >>= 1) l += __shfl_xor_sync(0xffffffffu, l, o);
            if (lane == 0) sm.sInv[r] = 1.0f / l;
        }
    }
    __syncthreads();

    // ---------- Phase 3: context = (p @ V) via tf32 MMA, with the attn
    //            GMEM write for tile jt overlapped into the same loop ----------
    {
        float acc3[8][4];
        #pragma unroll
        for (int nb = 0; nb < 8; ++nb)
            #pragma unroll
            for (int e = 0; e < 4; ++e) acc3[nb][e] = 0.f;

        // attn-write geometry: row ar, cols (tid&15)*8 within each tile
        const int ar   = tid >> 4;
        const int ac0  = (tid & 15) * 8;
        const float ainv = sm.sInv[ar];
        const float* __restrict__ arow = &sm.sS[ar * SS_STRIDE];
        float* __restrict__ adst = out_attn + ((size_t)bh * SQ + row0 + ar) * SQ;

        #pragma unroll
        for (int j = 0; j < 8; ++j) {
            int i  = i0 + j * NTHREADS;
            int t  = i >> 4;
            int d4 = (i & 15) << 2;
            uint32_t dst = (uint32_t)__cvta_generic_to_shared(&sm.sV[0][t * VT_STRIDE + d4]);
            CP_ASYNC16(dst, V + (size_t)t * DK + d4);
        }
        CP_COMMIT();

        #pragma unroll 1
        for (int jt = 0; jt < NTILES; ++jt) {
            const int stage = jt & 1;
            if (jt + 1 < NTILES) {
                const int nstage = stage ^ 1;
                #pragma unroll
                for (int j = 0; j < 8; ++j) {
                    int i  = i0 + j * NTHREADS;
                    int t  = i >> 4;
                    int d4 = (i & 15) << 2;
                    uint32_t dst = (uint32_t)__cvta_generic_to_shared(
                        &sm.sV[nstage][t * VT_STRIDE + d4]);
                    CP_ASYNC16(dst, V + ((size_t)(jt + 1) * TN + t) * DK + d4);
                }
                CP_COMMIT();
                CP_WAIT(1);
            } else {
                CP_WAIT(0);
            }
            __syncthreads();

            const float* __restrict__ sV = sm.sV[stage];
            #pragma unroll
            for (int kc2 = 0; kc2 < 2; ++kc2) {
                const int kb = warp * 16 + kc2 * 8;
                const float* pr = &sm.sS[gid * SS_STRIDE + jt * TN + kb + tig];
                uint32_t a0 = __float_as_uint(pr[0]);                  // exact tf32 (RNA'd p)
                uint32_t a1 = __float_as_uint(pr[8 * SS_STRIDE]);
                uint32_t a2 = __float_as_uint(pr[4]);
                uint32_t a3 = __float_as_uint(pr[8 * SS_STRIDE + 4]);
                #pragma unroll
                for (int nb = 0; nb < 8; ++nb) {
                    const int n0 = nb * 8;
                    uint32_t b0 = TF32_RN(__float_as_uint(sV[(kb + tig    ) * VT_STRIDE + n0 + gid]));
                    uint32_t b1 = TF32_RN(__float_as_uint(sV[(kb + tig + 4) * VT_STRIDE + n0 + gid]));
                    mma_tf32(acc3[nb], a0, a1, a2, a3, b0, b1);
                }
            }

            // overlapped attn write for tile jt (STG hides under MMA/LDS)
            {
                const int base = jt * TN + ac0;
                float4 p0 = *reinterpret_cast<const float4*>(&arow[base]);
                float4 p1 = *reinterpret_cast<const float4*>(&arow[base + 4]);
                p0.x *= ainv; p0.y *= ainv; p0.z *= ainv; p0.w *= ainv;
                p1.x *= ainv; p1.y *= ainv; p1.z *= ainv; p1.w *= ainv;
                *reinterpret_cast<float4*>(&adst[base])     = p0;
                *reinterpret_cast<float4*>(&adst[base + 4]) = p1;
            }
            __syncthreads();
        }

        // ---- reduce 8 warps' partials through smem (reuse sV stage 0) ----
        float* __restrict__ pbuf = sm.sV[0];      // [8][16][64] = 32 KB
        {
            float* base0 = &pbuf[((warp << 4) + gid    ) * 64 + 2 * tig];
            float* base1 = &pbuf[((warp << 4) + gid + 8) * 64 + 2 * tig];
            #pragma unroll
            for (int nb = 0; nb < 8; ++nb) {
                float2 t0, t1;
                t0.x = acc3[nb][0]; t0.y = acc3[nb][1];
                t1.x = acc3[nb][2]; t1.y = acc3[nb][3];
                *reinterpret_cast<float2*>(base0 + nb * 8) = t0;
                *reinterpret_cast<float2*>(base1 + nb * 8) = t1;
            }
        }
        __syncthreads();

        {
            int row = tid >> 4;
            int col = (tid & 15) * 4;
            float4 s = *reinterpret_cast<const float4*>(&pbuf[row * 64 + col]);
            #pragma unroll
            for (int w = 1; w < 8; ++w) {
                float4 t = *reinterpret_cast<const float4*>(&pbuf[((w << 4) + row) * 64 + col]);
                s.x += t.x; s.y += t.y; s.z += t.z; s.w += t.w;
            }
            float inv = sm.sInv[row];
            s.x *= inv; s.y *= inv; s.z *= inv; s.w *= inv;
            *reinterpret_cast<float4*>(
                out_ctx + ((size_t)bh * SQ + row0 + row) * DK + col) = s;
        }
    }
}

extern "C" void kernel_launch(void* const* d_in, const int* in_sizes, int n_in,
                              void* d_out, int out_size)
{
    const float* q = (const float*)d_in[0];
    const float* k = (const float*)d_in[1];
    const float* v = (const float*)d_in[2];
    const unsigned char* mraw = (const unsigned char*)d_in[3];

    float* out = (float*)d_out;
    float* out_ctx  = out;                           // [B,H,S,D]
    float* out_attn = out + (size_t)NBH * SQ * DK;   // [B,H,S,S]

    mask_canon_kernel<<<1, NTHREADS>>>(mraw);

    const int smem_bytes = (int)sizeof(Smem);
    cudaFuncSetAttribute(sdpa_tc_kernel,
                         cudaFuncAttributeMaxDynamicSharedMemorySize, smem_bytes);

    dim3 grid(SQ / TM, NBH);   // (128, 64)
    sdpa_tc_kernel<<<grid, NTHREADS, smem_bytes>>>(q, k, v, out_ctx, out_attn);
}